// round 1
// baseline (speedup 1.0000x reference)
#include <cuda_runtime.h>

// ---------------------------------------------------------------------------
// 2-layer LSTM, S=4096, B=64, I=14, H=256, O=1   (PyTorch gate order i,f,g,o)
//
// Persistent grid-synced kernel per layer. 128 CTAs x 128 threads.
// CTA bid owns hidden units {2*bid, 2*bid+1}. Thread (jj,b) owns one
// (hidden j, batch b) pair: its 4 gate accumulators + private c in registers.
// h (64KB, transposed [k][b]) is exchanged through L2 each step,
// double-buffered so one barrier per step suffices.
// ---------------------------------------------------------------------------

#define S_LEN 4096
#define BATCH 64
#define IN0   14
#define HID   256
#define NB    128
#define NT    128
#define HB    2          // hidden units per block

// ---- scratch (device globals; no allocation allowed) ----------------------
__device__ float   g_hs0T[(size_t)S_LEN * HID * BATCH];  // layer0 outputs, [t][k][b]  (256MB)
__device__ float   g_h0buf[2][HID * BATCH];              // layer0 h double buffer, [k][b]
__device__ float   g_h1buf[2][HID * BATCH];              // layer1 h double buffer, [k][b]
__device__ unsigned g_cnt0, g_cnt1;
__device__ unsigned g_gen0, g_gen1;

// ---- packed fp32x2 helpers -------------------------------------------------
__device__ __forceinline__ unsigned long long pack2(float x, float y) {
    unsigned long long r;
    asm("mov.b64 %0, {%1,%2};" : "=l"(r) : "f"(x), "f"(y));
    return r;
}
__device__ __forceinline__ void unpack2(unsigned long long v, float& x, float& y) {
    asm("mov.b64 {%0,%1}, %2;" : "=f"(x), "=f"(y) : "l"(v));
}
__device__ __forceinline__ unsigned long long ffma2(unsigned long long a,
                                                    unsigned long long b,
                                                    unsigned long long c) {
    unsigned long long d;
    asm("fma.rn.f32x2 %0, %1, %2, %3;" : "=l"(d) : "l"(a), "l"(b), "l"(c));
    return d;
}

// ---- activations -----------------------------------------------------------
__device__ __forceinline__ float sigmoidf_(float v) {
    return 1.0f / (1.0f + __expf(-v));     // large -v -> inf -> 0 (safe)
}
__device__ __forceinline__ float tanh_acc(float v) {
    float a = fabsf(v);
    float e = __expf(-2.0f * a);
    float r = __fdividef(1.0f - e, 1.0f + e);
    return v < 0.0f ? -r : r;
}

// ---- grid barrier (all NB CTAs co-resident: NB=128 <= 148 SMs) -------------
__device__ __forceinline__ void grid_barrier(unsigned* cnt, unsigned* gen) {
    __syncthreads();
    if (threadIdx.x == 0) {
        volatile unsigned* vgen = gen;
        unsigned g = *vgen;
        __threadfence();
        if (atomicAdd(cnt, 1u) == (unsigned)(NB - 1)) {
            *cnt = 0u;
            __threadfence();
            *vgen = g + 1u;
        } else {
            while (*vgen == g) { }
        }
        __threadfence();
    }
    __syncthreads();
}

__device__ __forceinline__ float warp_reduce(float p) {
    #pragma unroll
    for (int o = 16; o > 0; o >>= 1) p += __shfl_xor_sync(0xffffffffu, p, o);
    return p;
}

// ---------------------------------------------------------------------------
// Layer 0: x[t] (I=14) + recurrent H=256. Writes hs0T[t][k][b].
// ---------------------------------------------------------------------------
#define SMEM0 (HID*BATCH*4 + HB*HID*2*8 + HB*IN0*2*8 + BATCH*IN0*4)

extern "C" __global__ void __launch_bounds__(NT, 1)
lstm_layer0(const float* __restrict__ x,  const float* __restrict__ c0,
            const float* __restrict__ Wih, const float* __restrict__ Whh,
            const float* __restrict__ bih, const float* __restrict__ bhh)
{
    extern __shared__ char smem_raw[];
    float* sh_h  = (float*)smem_raw;                                   // [256][64]
    unsigned long long* sh_wp = (unsigned long long*)(smem_raw + HID*BATCH*4); // [HB][256][2]
    unsigned long long* sh_wi = sh_wp + HB*HID*2;                      // [HB][14][2]
    float* sh_x  = (float*)(sh_wi + HB*IN0*2);                         // [64][14]

    const int tid = threadIdx.x;
    const int b   = tid & 63;
    const int jj  = tid >> 6;
    const int j0  = blockIdx.x * HB;
    const int j   = j0 + jj;

    // pack recurrent weights: pair0=(Wi,Wf), pair1=(Wg,Wo) per (hidden,k)
    for (int idx = tid; idx < HB * HID; idx += NT) {
        int jl = idx >> 8, k = idx & 255;
        int jg = j0 + jl;
        sh_wp[(jl*HID + k)*2 + 0] = pack2(Whh[(0*HID + jg)*HID + k], Whh[(1*HID + jg)*HID + k]);
        sh_wp[(jl*HID + k)*2 + 1] = pack2(Whh[(2*HID + jg)*HID + k], Whh[(3*HID + jg)*HID + k]);
    }
    for (int idx = tid; idx < HB * IN0; idx += NT) {
        int jl = idx / IN0, d = idx % IN0;
        int jg = j0 + jl;
        sh_wi[(jl*IN0 + d)*2 + 0] = pack2(Wih[(0*HID + jg)*IN0 + d], Wih[(1*HID + jg)*IN0 + d]);
        sh_wi[(jl*IN0 + d)*2 + 1] = pack2(Wih[(2*HID + jg)*IN0 + d], Wih[(3*HID + jg)*IN0 + d]);
    }
    const unsigned long long bias_if =
        pack2(bih[0*HID + j] + bhh[0*HID + j], bih[1*HID + j] + bhh[1*HID + j]);
    const unsigned long long bias_go =
        pack2(bih[2*HID + j] + bhh[2*HID + j], bih[3*HID + j] + bhh[3*HID + j]);

    float c = c0[b*HID + j];                       // c0[0][b][j]
    const unsigned long long* wrow  = sh_wp + jj*HID*2;
    const unsigned long long* wirow = sh_wi + jj*IN0*2;
    __syncthreads();

    for (int t = 0; t < S_LEN; ++t) {
        // stage x[t] tile
        for (int idx = tid; idx < BATCH*IN0; idx += NT)
            sh_x[idx] = x[t*BATCH*IN0 + idx];
        // stage h (must bypass L1: modified every step within this launch)
        {
            const float4* src = (const float4*)g_h0buf[t & 1];
            float4* dst = (float4*)sh_h;
            #pragma unroll
            for (int i2 = 0; i2 < (HID*BATCH/4)/NT; ++i2)
                dst[tid + i2*NT] = __ldcg(src + tid + i2*NT);
        }
        __syncthreads();

        unsigned long long aif = bias_if, ago = bias_go;
        #pragma unroll
        for (int d = 0; d < IN0; ++d) {
            float xv = sh_x[b*IN0 + d];
            unsigned long long xp = pack2(xv, xv);
            aif = ffma2(xp, wirow[d*2 + 0], aif);
            ago = ffma2(xp, wirow[d*2 + 1], ago);
        }
        #pragma unroll 16
        for (int k = 0; k < HID; ++k) {
            float hv = sh_h[k*BATCH + b];
            unsigned long long hp = pack2(hv, hv);
            ulonglong2 wv = *(const ulonglong2*)(wrow + k*2);
            aif = ffma2(hp, wv.x, aif);
            ago = ffma2(hp, wv.y, ago);
        }
        float gi, gf, gg, go;
        unpack2(aif, gi, gf);
        unpack2(ago, gg, go);
        gi = sigmoidf_(gi); gf = sigmoidf_(gf);
        gg = tanh_acc(gg);  go = sigmoidf_(go);
        c = gf*c + gi*gg;
        float h = go * tanh_acc(c);

        g_h0buf[(t + 1) & 1][j*BATCH + b] = h;                  // next-step exchange
        g_hs0T[(size_t)t*(HID*BATCH) + j*BATCH + b] = h;        // layer1 input
        __threadfence();
        grid_barrier(&g_cnt0, &g_gen0);
    }
}

// ---------------------------------------------------------------------------
// Layer 1: input = hs0T[t] (K=256) + recurrent (K=256). Fused ReLU+FC output.
// sh_h uses stride 68 so the FC transposed read is only 4-way bank conflicted.
// ---------------------------------------------------------------------------
#define HSTR 68
#define SMEM1 (HID*HSTR*4 + HID*BATCH*4 + HB*HID*2*8 + HB*HID*2*8 + 64)

extern "C" __global__ void __launch_bounds__(NT, 1)
lstm_layer1(const float* __restrict__ c0,
            const float* __restrict__ Wih, const float* __restrict__ Whh,
            const float* __restrict__ bih, const float* __restrict__ bhh,
            const float* __restrict__ Wfc, const float* __restrict__ bfc,
            float* __restrict__ out)
{
    extern __shared__ char smem_raw[];
    float* sh_h   = (float*)smem_raw;                        // [256][68]
    float* sh_xin = sh_h + HID*HSTR;                         // [256][64]
    unsigned long long* sh_wph = (unsigned long long*)(sh_xin + HID*BATCH); // [HB][256][2]
    unsigned long long* sh_wpi = sh_wph + HB*HID*2;          // [HB][256][2]
    float* sh_red = (float*)(sh_wpi + HB*HID*2);             // [4]

    const int tid = threadIdx.x;
    const int b   = tid & 63;
    const int jj  = tid >> 6;
    const int j0  = blockIdx.x * HB;
    const int j   = j0 + jj;

    for (int idx = tid; idx < HB * HID; idx += NT) {
        int jl = idx >> 8, k = idx & 255;
        int jg = j0 + jl;
        sh_wph[(jl*HID + k)*2 + 0] = pack2(Whh[(0*HID + jg)*HID + k], Whh[(1*HID + jg)*HID + k]);
        sh_wph[(jl*HID + k)*2 + 1] = pack2(Whh[(2*HID + jg)*HID + k], Whh[(3*HID + jg)*HID + k]);
        sh_wpi[(jl*HID + k)*2 + 0] = pack2(Wih[(0*HID + jg)*HID + k], Wih[(1*HID + jg)*HID + k]);
        sh_wpi[(jl*HID + k)*2 + 1] = pack2(Wih[(2*HID + jg)*HID + k], Wih[(3*HID + jg)*HID + k]);
    }
    const unsigned long long bias_if =
        pack2(bih[0*HID + j] + bhh[0*HID + j], bih[1*HID + j] + bhh[1*HID + j]);
    const unsigned long long bias_go =
        pack2(bih[2*HID + j] + bhh[2*HID + j], bih[3*HID + j] + bhh[3*HID + j]);

    float c = c0[(BATCH + b)*HID + j];             // c0[1][b][j]
    const float wfc0 = Wfc[tid];
    const float wfc1 = Wfc[tid + 128];
    const float bf   = bfc[0];
    const unsigned long long* wrowh = sh_wph + jj*HID*2;
    const unsigned long long* wrowi = sh_wpi + jj*HID*2;
    __syncthreads();

    for (int t = 0; t < S_LEN; ++t) {
        // stage h1[t-1] (strided 68) — bypass L1
        {
            const float4* src = (const float4*)g_h1buf[t & 1];
            #pragma unroll
            for (int i2 = 0; i2 < (HID*BATCH/4)/NT; ++i2) {
                int idx = tid + i2*NT;               // float4 index, 16 per k-row
                float4 v = __ldcg(src + idx);
                int k  = idx >> 4;
                int b4 = idx & 15;
                *(float4*)(sh_h + k*HSTR + b4*4) = v;
            }
        }
        // stage hs0T[t] (written by a previous launch; L1 flushed per launch)
        {
            const float4* src = (const float4*)(g_hs0T + (size_t)t*(HID*BATCH));
            float4* dst = (float4*)sh_xin;
            #pragma unroll
            for (int i2 = 0; i2 < (HID*BATCH/4)/NT; ++i2)
                dst[tid + i2*NT] = src[tid + i2*NT];
        }
        __syncthreads();

        // fused FC for row t-1 (sh_h currently holds h1[t-1]); deterministic
        if (t > 0 && blockIdx.x < BATCH) {
            int bb = blockIdx.x;
            float p = fmaxf(sh_h[tid*HSTR + bb], 0.0f) * wfc0
                    + fmaxf(sh_h[(tid + 128)*HSTR + bb], 0.0f) * wfc1;
            p = warp_reduce(p);
            if ((tid & 31) == 0) sh_red[tid >> 5] = p;
            __syncthreads();
            if (tid == 0)
                out[(t - 1)*BATCH + bb] = sh_red[0] + sh_red[1] + sh_red[2] + sh_red[3] + bf;
        }

        unsigned long long aif = bias_if, ago = bias_go;
        #pragma unroll 16
        for (int k = 0; k < HID; ++k) {             // input contribution
            float xv = sh_xin[k*BATCH + b];
            unsigned long long xp = pack2(xv, xv);
            ulonglong2 wv = *(const ulonglong2*)(wrowi + k*2);
            aif = ffma2(xp, wv.x, aif);
            ago = ffma2(xp, wv.y, ago);
        }
        #pragma unroll 16
        for (int k = 0; k < HID; ++k) {             // recurrent contribution
            float hv = sh_h[k*HSTR + b];
            unsigned long long hp = pack2(hv, hv);
            ulonglong2 wv = *(const ulonglong2*)(wrowh + k*2);
            aif = ffma2(hp, wv.x, aif);
            ago = ffma2(hp, wv.y, ago);
        }
        float gi, gf, gg, go;
        unpack2(aif, gi, gf);
        unpack2(ago, gg, go);
        gi = sigmoidf_(gi); gf = sigmoidf_(gf);
        gg = tanh_acc(gg);  go = sigmoidf_(go);
        c = gf*c + gi*gg;
        float h = go * tanh_acc(c);

        g_h1buf[(t + 1) & 1][j*BATCH + b] = h;
        __threadfence();
        grid_barrier(&g_cnt1, &g_gen1);
    }

    // final FC row (t = S_LEN-1): h1[4095] sits in g_h1buf[S_LEN & 1] = buf[0]
    if (blockIdx.x < BATCH) {
        int bb = blockIdx.x;
        float v1 = __ldcg(&g_h1buf[0][tid*BATCH + bb]);
        float v2 = __ldcg(&g_h1buf[0][(tid + 128)*BATCH + bb]);
        float p = fmaxf(v1, 0.0f)*wfc0 + fmaxf(v2, 0.0f)*wfc1;
        p = warp_reduce(p);
        if ((tid & 31) == 0) sh_red[tid >> 5] = p;
        __syncthreads();
        if (tid == 0)
            out[(S_LEN - 1)*BATCH + bb] = sh_red[0] + sh_red[1] + sh_red[2] + sh_red[3] + bf;
    }
}

// ---------------------------------------------------------------------------
// Init: reset barrier state, transpose h0 -> [k][b] double-buffer slot 0.
// ---------------------------------------------------------------------------
extern "C" __global__ void lstm_init(const float* __restrict__ h0)
{
    int i = blockIdx.x * blockDim.x + threadIdx.x;
    if (i == 0) { g_cnt0 = 0; g_cnt1 = 0; g_gen0 = 0; g_gen1 = 0; }
    for (int idx = i; idx < 2 * HID * BATCH; idx += gridDim.x * blockDim.x) {
        int l = idx >> 14;
        int r = idx & 16383;
        int k = r >> 6;
        int b = r & 63;
        float v = h0[(l*BATCH + b)*HID + k];
        if (l == 0) g_h0buf[0][k*BATCH + b] = v;
        else        g_h1buf[0][k*BATCH + b] = v;
    }
}

// ---------------------------------------------------------------------------
extern "C" void kernel_launch(void* const* d_in, const int* in_sizes, int n_in,
                              void* d_out, int out_size)
{
    const float* x    = (const float*)d_in[0];
    const float* h0   = (const float*)d_in[1];
    const float* c0   = (const float*)d_in[2];
    const float* Wih0 = (const float*)d_in[3];
    const float* Whh0 = (const float*)d_in[4];
    const float* bih0 = (const float*)d_in[5];
    const float* bhh0 = (const float*)d_in[6];
    const float* Wih1 = (const float*)d_in[7];
    const float* Whh1 = (const float*)d_in[8];
    const float* bih1 = (const float*)d_in[9];
    const float* bhh1 = (const float*)d_in[10];
    const float* Wfc  = (const float*)d_in[11];
    const float* bfc  = (const float*)d_in[12];
    float* out = (float*)d_out;

    cudaFuncSetAttribute(lstm_layer0, cudaFuncAttributeMaxDynamicSharedMemorySize, SMEM0);
    cudaFuncSetAttribute(lstm_layer1, cudaFuncAttributeMaxDynamicSharedMemorySize, SMEM1);

    lstm_init<<<64, 256>>>(h0);
    lstm_layer0<<<NB, NT, SMEM0>>>(x, c0, Wih0, Whh0, bih0, bhh0);
    lstm_layer1<<<NB, NT, SMEM1>>>(c0, Wih1, Whh1, bih1, bhh1, Wfc, bfc, out);
}

// round 2
// speedup vs baseline: 1.2055x; 1.2055x over previous
#include <cuda_runtime.h>
#include <cstdint>

// ---------------------------------------------------------------------------
// Fused 2-layer LSTM, S=4096, B=64, I=14, H=256, O=1 (gate order i,f,g,o)
//
// ONE persistent kernel, 128 CTAs x 256 threads, software-pipelined:
//   iteration t: warps 0-3 compute h0[t]   (layer0, needs h0[t-1])
//                warps 4-7 compute h1[t-1] (layer1, needs h0[t-1], h1[t-2])
// h0[t-1] and h1[t-2] are broadcast through L2 each iteration (cp.async.cg),
// double-buffered in global so ONE release/acquire barrier per iteration
// suffices. hs0 never touches DRAM: layer1 reads the same smem h0 buffer.
// h stored k-pair-interleaved: [k/2][b][2] so the FFMA2 multiplier is a
// native LDS.64 (accumulator lo/hi = even/odd-k partials, summed at the end).
// ---------------------------------------------------------------------------

#define S_LEN 4096
#define BATCH 64
#define IN0   14
#define HID   256
#define KP    (HID/2)
#define NB    128
#define NT    256
#define HB    2

// ---- global scratch --------------------------------------------------------
__device__ float    g_h0buf[2][HID * BATCH];   // [(k>>1)*64+b]*2 + (k&1)
__device__ float    g_h1buf[2][HID * BATCH];
__device__ unsigned g_bar;                     // monotone arrival counter

// ---- packed fp32x2 helpers -------------------------------------------------
__device__ __forceinline__ unsigned long long pack2(float x, float y) {
    unsigned long long r;
    asm("mov.b64 %0, {%1,%2};" : "=l"(r) : "f"(x), "f"(y));
    return r;
}
__device__ __forceinline__ void unpack2(unsigned long long v, float& x, float& y) {
    asm("mov.b64 {%0,%1}, %2;" : "=f"(x), "=f"(y) : "l"(v));
}
__device__ __forceinline__ unsigned long long ffma2(unsigned long long a,
                                                    unsigned long long b,
                                                    unsigned long long c) {
    unsigned long long d;
    asm("fma.rn.f32x2 %0, %1, %2, %3;" : "=l"(d) : "l"(a), "l"(b), "l"(c));
    return d;
}

// ---- activations -----------------------------------------------------------
__device__ __forceinline__ float sigmoidf_(float v) {
    return 1.0f / (1.0f + __expf(-v));
}
__device__ __forceinline__ float tanh_acc(float v) {
    float a = fabsf(v);
    float e = __expf(-2.0f * a);
    float r = __fdividef(1.0f - e, 1.0f + e);
    return v < 0.0f ? -r : r;
}

// ---- sync primitives (op-level release/acquire: no CCTL.IVALL, no MEMBAR) --
__device__ __forceinline__ void red_rel_add(unsigned* p) {
    asm volatile("red.release.gpu.global.add.u32 [%0], %1;" :: "l"(p), "r"(1u) : "memory");
}
__device__ __forceinline__ unsigned ld_acq(const unsigned* p) {
    unsigned v;
    asm volatile("ld.acquire.gpu.global.u32 %0, [%1];" : "=r"(v) : "l"(p) : "memory");
    return v;
}
__device__ __forceinline__ void cp16(uint32_t dst, const void* src) {
    asm volatile("cp.async.cg.shared.global [%0], [%1], 16;" :: "r"(dst), "l"(src));
}

__device__ __forceinline__ float warp_reduce(float p) {
    #pragma unroll
    for (int o = 16; o > 0; o >>= 1) p += __shfl_xor_sync(0xffffffffu, p, o);
    return p;
}

// ---- smem layout (bytes) ---------------------------------------------------
#define SH_H0   0                       // 65536  float[HID*BATCH] pair-interleaved
#define SH_H1   65536                   // 65536
#define SH_W0   131072                  // 8192   ulonglong2[HB*KP*2]  (Whh0)
#define SH_WI1  139264                  // 8192   (Wih1)
#define SH_WH1  147456                  // 8192   (Whh1)
#define SH_WI0  155648                  // 512    float4[HB*IN0]
#define SH_X    156160                  // 7168   float[2][BATCH*IN0]
#define SH_RED  163328                  // 32
#define SMEM_TOTAL 163392

extern "C" __global__ void __launch_bounds__(NT, 1)
lstm_fused(const float* __restrict__ x,   const float* __restrict__ c0,
           const float* __restrict__ Wih0, const float* __restrict__ Whh0,
           const float* __restrict__ bih0, const float* __restrict__ bhh0,
           const float* __restrict__ Wih1, const float* __restrict__ Whh1,
           const float* __restrict__ bih1, const float* __restrict__ bhh1,
           const float* __restrict__ Wfc,  const float* __restrict__ bfc,
           float* __restrict__ out)
{
    extern __shared__ char smem[];
    float*      sh_h0  = (float*)(smem + SH_H0);
    float*      sh_h1  = (float*)(smem + SH_H1);
    ulonglong2* w0     = (ulonglong2*)(smem + SH_W0);
    ulonglong2* wi1    = (ulonglong2*)(smem + SH_WI1);
    ulonglong2* wh1    = (ulonglong2*)(smem + SH_WH1);
    float4*     wi0    = (float4*)(smem + SH_WI0);
    float*      shx    = (float*)(smem + SH_X);
    float*      red4   = (float*)(smem + SH_RED);

    const uint32_t smem_h0 = (uint32_t)__cvta_generic_to_shared(sh_h0);
    const uint32_t smem_h1 = (uint32_t)__cvta_generic_to_shared(sh_h1);

    const int tid  = threadIdx.x;
    const int bid  = blockIdx.x;
    const int role = tid >> 7;          // 0: layer0 (+FC), 1: layer1
    const int rt_  = tid & 127;
    const int b    = rt_ & 63;
    const int jj   = rt_ >> 6;
    const int j0   = bid * HB;
    const int j    = j0 + jj;

    // ---- preload packed weights -------------------------------------------
    for (int idx = tid; idx < HB * KP; idx += NT) {
        int jl = idx >> 7, kp = idx & (KP - 1);
        int jg = j0 + jl;
        int k0 = 2 * kp;
        w0[idx*2+0] = make_ulonglong2(
            pack2(Whh0[(0*HID+jg)*HID + k0], Whh0[(0*HID+jg)*HID + k0+1]),
            pack2(Whh0[(1*HID+jg)*HID + k0], Whh0[(1*HID+jg)*HID + k0+1]));
        w0[idx*2+1] = make_ulonglong2(
            pack2(Whh0[(2*HID+jg)*HID + k0], Whh0[(2*HID+jg)*HID + k0+1]),
            pack2(Whh0[(3*HID+jg)*HID + k0], Whh0[(3*HID+jg)*HID + k0+1]));
        wi1[idx*2+0] = make_ulonglong2(
            pack2(Wih1[(0*HID+jg)*HID + k0], Wih1[(0*HID+jg)*HID + k0+1]),
            pack2(Wih1[(1*HID+jg)*HID + k0], Wih1[(1*HID+jg)*HID + k0+1]));
        wi1[idx*2+1] = make_ulonglong2(
            pack2(Wih1[(2*HID+jg)*HID + k0], Wih1[(2*HID+jg)*HID + k0+1]),
            pack2(Wih1[(3*HID+jg)*HID + k0], Wih1[(3*HID+jg)*HID + k0+1]));
        wh1[idx*2+0] = make_ulonglong2(
            pack2(Whh1[(0*HID+jg)*HID + k0], Whh1[(0*HID+jg)*HID + k0+1]),
            pack2(Whh1[(1*HID+jg)*HID + k0], Whh1[(1*HID+jg)*HID + k0+1]));
        wh1[idx*2+1] = make_ulonglong2(
            pack2(Whh1[(2*HID+jg)*HID + k0], Whh1[(2*HID+jg)*HID + k0+1]),
            pack2(Whh1[(3*HID+jg)*HID + k0], Whh1[(3*HID+jg)*HID + k0+1]));
    }
    for (int idx = tid; idx < HB * IN0; idx += NT) {
        int jl = idx / IN0, d = idx % IN0;
        int jg = j0 + jl;
        wi0[idx] = make_float4(Wih0[(0*HID+jg)*IN0 + d], Wih0[(1*HID+jg)*IN0 + d],
                               Wih0[(2*HID+jg)*IN0 + d], Wih0[(3*HID+jg)*IN0 + d]);
    }

    // per-thread biases / state
    float bi, bfv, bg, bo, c;
    if (role == 0) {
        bi  = bih0[0*HID+j] + bhh0[0*HID+j];
        bfv = bih0[1*HID+j] + bhh0[1*HID+j];
        bg  = bih0[2*HID+j] + bhh0[2*HID+j];
        bo  = bih0[3*HID+j] + bhh0[3*HID+j];
        c   = c0[b*HID + j];                       // c0[0][b][j]
    } else {
        bi  = bih1[0*HID+j] + bhh1[0*HID+j];
        bfv = bih1[1*HID+j] + bhh1[1*HID+j];
        bg  = bih1[2*HID+j] + bhh1[2*HID+j];
        bo  = bih1[3*HID+j] + bhh1[3*HID+j];
        c   = c0[(BATCH + b)*HID + j];             // c0[1][b][j]
    }
    const float wfc0 = Wfc[rt_];
    const float wfc1 = Wfc[rt_ + 128];
    const float bfc0 = bfc[0];

    // stage x[0]
    for (int idx = tid; idx < BATCH*IN0; idx += NT) shx[idx] = x[idx];
    __syncthreads();

    const ulonglong2* wr0  = w0  + jj * KP * 2;
    const ulonglong2* wri1 = wi1 + jj * KP * 2;
    const ulonglong2* wrh1 = wh1 + jj * KP * 2;

    for (int t = 0; t <= S_LEN; ++t) {
        // ---- load phase: broadcast h0[t-1], h1[t-2] into smem (L2 only) ----
        {
            const float4* s0 = (const float4*)g_h0buf[t & 1];
            const float4* s1 = (const float4*)g_h1buf[t & 1];
            #pragma unroll
            for (int i = 0; i < 16; ++i) {
                int ci = tid + i * NT;
                cp16(smem_h0 + ci * 16, s0 + ci);
            }
            #pragma unroll
            for (int i = 0; i < 16; ++i) {
                int ci = tid + i * NT;
                cp16(smem_h1 + ci * 16, s1 + ci);
            }
            asm volatile("cp.async.wait_all;" ::: "memory");
            __syncthreads();
        }

        if (role == 0) {
            // ---- fused FC for h1[t-2] (now in sh_h1) -----------------------
            if (t >= 2 && bid < BATCH) {
                int i1x = ((rt_ >> 1)*BATCH + bid)*2 + (rt_ & 1);
                int i2x = (((rt_ + 128) >> 1)*BATCH + bid)*2 + (rt_ & 1);
                float p = fmaxf(sh_h1[i1x], 0.0f) * wfc0
                        + fmaxf(sh_h1[i2x], 0.0f) * wfc1;
                p = warp_reduce(p);
                if ((rt_ & 31) == 0) red4[rt_ >> 5] = p;
                asm volatile("bar.sync 1, 128;" ::: "memory");
                if (rt_ == 0)
                    out[(t - 2)*BATCH + bid] = red4[0]+red4[1]+red4[2]+red4[3] + bfc0;
            }
            // ---- layer0 step t ---------------------------------------------
            if (t < S_LEN) {
                const float* xr = shx + (t & 1)*(BATCH*IN0) + b*IN0;
                float si = bi, sf = bfv, sg = bg, so = bo;
                const float4* wi = wi0 + jj * IN0;
                #pragma unroll
                for (int d = 0; d < IN0; ++d) {
                    float xv = xr[d]; float4 w = wi[d];
                    si = fmaf(xv, w.x, si); sf = fmaf(xv, w.y, sf);
                    sg = fmaf(xv, w.z, sg); so = fmaf(xv, w.w, so);
                }
                unsigned long long aI = pack2(si, 0.f), aF = pack2(sf, 0.f);
                unsigned long long aG = pack2(sg, 0.f), aO = pack2(so, 0.f);
                const unsigned long long* hp = (const unsigned long long*)sh_h0 + b;
                #pragma unroll 8
                for (int kp = 0; kp < KP; ++kp) {
                    unsigned long long hv = hp[kp * 64];
                    ulonglong2 wa = wr0[kp*2], wb = wr0[kp*2+1];
                    aI = ffma2(hv, wa.x, aI); aF = ffma2(hv, wa.y, aF);
                    aG = ffma2(hv, wb.x, aG); aO = ffma2(hv, wb.y, aO);
                }
                float p0, p1, gi, gf, gg, go;
                unpack2(aI, p0, p1); gi = sigmoidf_(p0 + p1);
                unpack2(aF, p0, p1); gf = sigmoidf_(p0 + p1);
                unpack2(aG, p0, p1); gg = tanh_acc(p0 + p1);
                unpack2(aO, p0, p1); go = sigmoidf_(p0 + p1);
                c = gf*c + gi*gg;
                float h = go * tanh_acc(c);
                g_h0buf[(t + 1) & 1][((j >> 1)*BATCH + b)*2 + (j & 1)] = h;
            }
        } else {
            // ---- layer1: compute h1[t-1] from h0[t-1] (sh_h0), h1[t-2] -----
            if (t >= 1) {
                unsigned long long aI = pack2(bi, 0.f), aF = pack2(bfv, 0.f);
                unsigned long long aG = pack2(bg, 0.f), aO = pack2(bo, 0.f);
                const unsigned long long* hp0 = (const unsigned long long*)sh_h0 + b;
                #pragma unroll 8
                for (int kp = 0; kp < KP; ++kp) {
                    unsigned long long hv = hp0[kp * 64];
                    ulonglong2 wa = wri1[kp*2], wb = wri1[kp*2+1];
                    aI = ffma2(hv, wa.x, aI); aF = ffma2(hv, wa.y, aF);
                    aG = ffma2(hv, wb.x, aG); aO = ffma2(hv, wb.y, aO);
                }
                const unsigned long long* hp1 = (const unsigned long long*)sh_h1 + b;
                #pragma unroll 8
                for (int kp = 0; kp < KP; ++kp) {
                    unsigned long long hv = hp1[kp * 64];
                    ulonglong2 wa = wrh1[kp*2], wb = wrh1[kp*2+1];
                    aI = ffma2(hv, wa.x, aI); aF = ffma2(hv, wa.y, aF);
                    aG = ffma2(hv, wb.x, aG); aO = ffma2(hv, wb.y, aO);
                }
                float p0, p1, gi, gf, gg, go;
                unpack2(aI, p0, p1); gi = sigmoidf_(p0 + p1);
                unpack2(aF, p0, p1); gf = sigmoidf_(p0 + p1);
                unpack2(aG, p0, p1); gg = tanh_acc(p0 + p1);
                unpack2(aO, p0, p1); go = sigmoidf_(p0 + p1);
                c = gf*c + gi*gg;
                float h = go * tanh_acc(c);
                g_h1buf[(t + 1) & 1][((j >> 1)*BATCH + b)*2 + (j & 1)] = h;
            }
        }

        // ---- barrier: arrive, overlap x-staging with propagation, wait -----
        __syncthreads();                               // all stores issued
        if (tid == 0) red_rel_add(&g_bar);
        if (t + 1 < S_LEN) {                           // stage x[t+1]
            const float* xs = x + (size_t)(t + 1)*BATCH*IN0;
            float* xd = shx + ((t + 1) & 1)*(BATCH*IN0);
            for (int idx = tid; idx < BATCH*IN0; idx += NT) xd[idx] = xs[idx];
        }
        if (tid == 0) {
            unsigned target = (unsigned)NB * (unsigned)(t + 1);
            unsigned v = ld_acq(&g_bar);
            while (v < target) { __nanosleep(40); v = ld_acq(&g_bar); }
        }
        __syncthreads();
    }

    // ---- final FC row (h1[4095] lives in g_h1buf[1]) -----------------------
    if (role == 0 && bid < BATCH) {
        int i1x = ((rt_ >> 1)*BATCH + bid)*2 + (rt_ & 1);
        int i2x = (((rt_ + 128) >> 1)*BATCH + bid)*2 + (rt_ & 1);
        float v1 = __ldcg(&g_h1buf[1][i1x]);
        float v2 = __ldcg(&g_h1buf[1][i2x]);
        float p = fmaxf(v1, 0.0f)*wfc0 + fmaxf(v2, 0.0f)*wfc1;
        p = warp_reduce(p);
        if ((rt_ & 31) == 0) red4[rt_ >> 5] = p;
        asm volatile("bar.sync 1, 128;" ::: "memory");
        if (rt_ == 0)
            out[(S_LEN - 1)*BATCH + bid] = red4[0]+red4[1]+red4[2]+red4[3] + bfc0;
    }
}

// ---------------------------------------------------------------------------
// Init: reset barrier counter; transpose h0 into pair-interleaved buffers.
// g_h0buf[0] = initial h0 (read at t=0); g_h1buf[1] = initial h1 (read at t=1).
// ---------------------------------------------------------------------------
extern "C" __global__ void lstm_init(const float* __restrict__ h0)
{
    int i = blockIdx.x * blockDim.x + threadIdx.x;
    if (i == 0) g_bar = 0u;
    for (int idx = i; idx < 2 * HID * BATCH; idx += gridDim.x * blockDim.x) {
        int l = idx >> 14;
        int r = idx & 16383;
        int k = r >> 6;
        int b = r & 63;
        float v = h0[(l*BATCH + b)*HID + k];
        int di = ((k >> 1)*BATCH + b)*2 + (k & 1);
        if (l == 0) g_h0buf[0][di] = v;
        else        g_h1buf[1][di] = v;
    }
}

// ---------------------------------------------------------------------------
extern "C" void kernel_launch(void* const* d_in, const int* in_sizes, int n_in,
                              void* d_out, int out_size)
{
    const float* x    = (const float*)d_in[0];
    const float* h0   = (const float*)d_in[1];
    const float* c0   = (const float*)d_in[2];
    const float* Wih0 = (const float*)d_in[3];
    const float* Whh0 = (const float*)d_in[4];
    const float* bih0 = (const float*)d_in[5];
    const float* bhh0 = (const float*)d_in[6];
    const float* Wih1 = (const float*)d_in[7];
    const float* Whh1 = (const float*)d_in[8];
    const float* bih1 = (const float*)d_in[9];
    const float* bhh1 = (const float*)d_in[10];
    const float* Wfc  = (const float*)d_in[11];
    const float* bfc  = (const float*)d_in[12];
    float* out = (float*)d_out;

    cudaFuncSetAttribute(lstm_fused, cudaFuncAttributeMaxDynamicSharedMemorySize, SMEM_TOTAL);

    lstm_init<<<64, 256>>>(h0);
    lstm_fused<<<NB, NT, SMEM_TOTAL>>>(x, c0, Wih0, Whh0, bih0, bhh0,
                                       Wih1, Whh1, bih1, bhh1, Wfc, bfc, out);
}

// round 3
// speedup vs baseline: 2.4307x; 2.0163x over previous
#include <cuda_runtime.h>
#include <cstdint>

// ---------------------------------------------------------------------------
// Fused 2-layer LSTM, S=4096, B=64, I=14, H=256, O=1 (gate order i,f,g,o)
//
// ONE persistent kernel, 128 CTAs x 256 threads.
//   thread = (role, kh, b):  role 0 = layer0 (+FC), role 1 = layer1
//   Each thread accumulates BOTH of the CTA's 2 hidden units (j0, j0+1)
//   over its k-half; partials combined via an 8-float smem exchange.
// h exchange via global double buffers, loaded per step with cp.async +
// two mbarriers (h0 / h1) so compute starts as soon as h0 lands.
// One global release/acquire barrier per step.
// ---------------------------------------------------------------------------

#define S_LEN 4096
#define BATCH 64
#define IN0   14
#define HID   256
#define NB    128
#define NT    256
#define KPH   64          // k-pairs per half

// ---- global scratch --------------------------------------------------------
__device__ float    g_h0buf[2][HID * BATCH];   // float idx ((j>>1)*64+b)*2+(j&1)
__device__ float    g_h1buf[2][HID * BATCH];
__device__ unsigned g_bar;

// ---- packed fp32x2 helpers -------------------------------------------------
__device__ __forceinline__ unsigned long long pack2(float x, float y) {
    unsigned long long r;
    asm("mov.b64 %0, {%1,%2};" : "=l"(r) : "f"(x), "f"(y));
    return r;
}
__device__ __forceinline__ void unpack2(unsigned long long v, float& x, float& y) {
    asm("mov.b64 {%0,%1}, %2;" : "=f"(x), "=f"(y) : "l"(v));
}
__device__ __forceinline__ unsigned long long ffma2(unsigned long long a,
                                                    unsigned long long b,
                                                    unsigned long long c) {
    unsigned long long d;
    asm("fma.rn.f32x2 %0, %1, %2, %3;" : "=l"(d) : "l"(a), "l"(b), "l"(c));
    return d;
}

// ---- activations -----------------------------------------------------------
__device__ __forceinline__ float sigmoidf_(float v) {
    return 1.0f / (1.0f + __expf(-v));
}
__device__ __forceinline__ float tanh_acc(float v) {
    float a = fabsf(v);
    float e = __expf(-2.0f * a);
    float r = __fdividef(1.0f - e, 1.0f + e);
    return v < 0.0f ? -r : r;
}

// ---- sync primitives -------------------------------------------------------
__device__ __forceinline__ void red_rel_add(unsigned* p) {
    asm volatile("red.release.gpu.global.add.u32 [%0], %1;" :: "l"(p), "r"(1u) : "memory");
}
__device__ __forceinline__ unsigned ld_acq(const unsigned* p) {
    unsigned v;
    asm volatile("ld.acquire.gpu.global.u32 %0, [%1];" : "=r"(v) : "l"(p) : "memory");
    return v;
}
__device__ __forceinline__ void cp16(uint32_t dst, const void* src) {
    asm volatile("cp.async.cg.shared.global [%0], [%1], 16;" :: "r"(dst), "l"(src));
}
__device__ __forceinline__ void mbar_init(uint32_t a, uint32_t cnt) {
    asm volatile("mbarrier.init.shared.b64 [%0], %1;" :: "r"(a), "r"(cnt) : "memory");
}
__device__ __forceinline__ void cp_arrive_noinc(uint32_t a) {
    asm volatile("cp.async.mbarrier.arrive.noinc.shared.b64 [%0];" :: "r"(a) : "memory");
}
__device__ __forceinline__ void mbar_wait_parity(uint32_t addr, uint32_t parity) {
    asm volatile(
        "{\n\t.reg .pred P;\n"
        "MW_%=:\n\t"
        "mbarrier.try_wait.parity.shared::cta.b64 P, [%0], %1;\n\t"
        "@!P bra MW_%=;\n\t}"
        :: "r"(addr), "r"(parity) : "memory");
}
__device__ __forceinline__ float warp_reduce(float p) {
    #pragma unroll
    for (int o = 16; o > 0; o >>= 1) p += __shfl_xor_sync(0xffffffffu, p, o);
    return p;
}

// ---- smem layout (bytes) ---------------------------------------------------
#define SH_H0    0         // 65536  ull[128][64]  (h pairs, [kp][b])
#define SH_H1    65536     // 65536
#define SH_W0    131072    // 8192   ull[(kh*64+kp)*8 + j*4 + g]  (Whh0)
#define SH_WI1   139264    // 8192   (Wih1)
#define SH_WH1   147456    // 8192   (Whh1)
#define SH_WI0   155648    // 512    float4[2][14]
#define SH_X     156160    // 7168   float[2][896]
#define SH_PART  163328    // 8192   float[256][8]
#define SH_RED   171520    // 32
#define SH_MBAR  171552    // 16     two mbarriers
#define SMEM_TOTAL 171568

extern "C" __global__ void __launch_bounds__(NT, 1)
lstm_fused(const float* __restrict__ x,   const float* __restrict__ c0,
           const float* __restrict__ Wih0, const float* __restrict__ Whh0,
           const float* __restrict__ bih0, const float* __restrict__ bhh0,
           const float* __restrict__ Wih1, const float* __restrict__ Whh1,
           const float* __restrict__ bih1, const float* __restrict__ bhh1,
           const float* __restrict__ Wfc,  const float* __restrict__ bfc,
           float* __restrict__ out)
{
    extern __shared__ char smem[];
    unsigned long long* sh_h0u = (unsigned long long*)(smem + SH_H0);
    unsigned long long* sh_h1u = (unsigned long long*)(smem + SH_H1);
    float*              sh_h1f = (float*)(smem + SH_H1);
    unsigned long long* w0     = (unsigned long long*)(smem + SH_W0);
    unsigned long long* wi1    = (unsigned long long*)(smem + SH_WI1);
    unsigned long long* wh1    = (unsigned long long*)(smem + SH_WH1);
    float4*             wi0    = (float4*)(smem + SH_WI0);
    float*              shx    = (float*)(smem + SH_X);
    float*              part   = (float*)(smem + SH_PART);
    float*              red4   = (float*)(smem + SH_RED);

    const uint32_t smem_h0 = (uint32_t)__cvta_generic_to_shared(smem + SH_H0);
    const uint32_t smem_h1 = (uint32_t)__cvta_generic_to_shared(smem + SH_H1);
    const uint32_t mb0     = (uint32_t)__cvta_generic_to_shared(smem + SH_MBAR);
    const uint32_t mb1     = mb0 + 8;

    const int tid  = threadIdx.x;
    const int bid  = blockIdx.x;
    const int role = tid >> 7;          // 0: layer0+FC, 1: layer1
    const int rt_  = tid & 127;
    const int kh   = (tid >> 6) & 1;    // k-half
    const int b    = tid & 63;
    const int j0   = bid * 2;
    const int jown = j0 + kh;           // hidden unit this thread finalizes

    // ---- init mbarriers ----------------------------------------------------
    if (tid == 0) { mbar_init(mb0, NT); mbar_init(mb1, NT); }

    // ---- preload packed weights: slot ((kh*64+kp)*8 + j*4 + g) -------------
    for (int idx = tid; idx < 1024; idx += NT) {
        int g  = idx & 3;
        int jl = (idx >> 2) & 1;
        int kp = (idx >> 3) & 63;
        int k2 = idx >> 9;              // kh
        int k0 = (k2 * KPH + kp) * 2;
        int row = (g * HID + j0 + jl) * HID;
        int slot = ((k2 * KPH + kp) * 8) + jl * 4 + g;
        w0 [slot] = pack2(Whh0[row + k0], Whh0[row + k0 + 1]);
        wi1[slot] = pack2(Wih1[row + k0], Wih1[row + k0 + 1]);
        wh1[slot] = pack2(Whh1[row + k0], Whh1[row + k0 + 1]);
    }
    for (int idx = tid; idx < 2 * IN0; idx += NT) {
        int jl = idx / IN0, d = idx % IN0;
        wi0[jl * IN0 + d] = make_float4(
            Wih0[(0*HID + j0 + jl)*IN0 + d], Wih0[(1*HID + j0 + jl)*IN0 + d],
            Wih0[(2*HID + j0 + jl)*IN0 + d], Wih0[(3*HID + j0 + jl)*IN0 + d]);
    }

    // per-thread biases / state (for jown)
    float bG0, bG1, bG2, bG3, c;
    if (role == 0) {
        bG0 = bih0[0*HID+jown] + bhh0[0*HID+jown];
        bG1 = bih0[1*HID+jown] + bhh0[1*HID+jown];
        bG2 = bih0[2*HID+jown] + bhh0[2*HID+jown];
        bG3 = bih0[3*HID+jown] + bhh0[3*HID+jown];
        c   = c0[b*HID + jown];
    } else {
        bG0 = bih1[0*HID+jown] + bhh1[0*HID+jown];
        bG1 = bih1[1*HID+jown] + bhh1[1*HID+jown];
        bG2 = bih1[2*HID+jown] + bhh1[2*HID+jown];
        bG3 = bih1[3*HID+jown] + bhh1[3*HID+jown];
        c   = c0[BATCH*HID + b*HID + jown];
    }
    const float wfc0 = Wfc[rt_];
    const float wfc1 = Wfc[rt_ + 128];
    const float bfc0 = bfc[0];

    // stage x[0]
    for (int idx = tid; idx < BATCH*IN0; idx += NT) shx[idx] = x[idx];
    __syncthreads();

    const int kpb = kh * KPH;           // base k-pair for this thread's half
    const unsigned long long* wr0  = w0  + (size_t)kpb * 8;
    const unsigned long long* wri1 = wi1 + (size_t)kpb * 8;
    const unsigned long long* wrh1 = wh1 + (size_t)kpb * 8;

    for (int t = 0; t <= S_LEN; ++t) {
        const uint32_t par = (uint32_t)(t & 1);

        // ---- issue cp.async: h0 -> M0, h1 -> M1 ---------------------------
        {
            const float4* s0 = (const float4*)g_h0buf[t & 1];
            const float4* s1 = (const float4*)g_h1buf[t & 1];
            #pragma unroll
            for (int i = 0; i < 16; ++i) {
                int ci = tid + i * NT;
                cp16(smem_h0 + ci * 16, s0 + ci);
            }
            cp_arrive_noinc(mb0);
            #pragma unroll
            for (int i = 0; i < 16; ++i) {
                int ci = tid + i * NT;
                cp16(smem_h1 + ci * 16, s1 + ci);
            }
            cp_arrive_noinc(mb1);
        }

        if (role == 0) {
            // ================= layer0 (k-half) + FC =========================
            mbar_wait_parity(mb0, par);
            unsigned long long a0=0,a1=0,a2=0,a3=0,a4=0,a5=0,a6=0,a7=0;
            float xi=0.f, xf=0.f, xg=0.f, xo=0.f;
            if (t < S_LEN) {
                const unsigned long long* hp = sh_h0u + (size_t)kpb * 64 + b;
                #pragma unroll 8
                for (int kp = 0; kp < KPH; ++kp) {
                    unsigned long long hv = hp[kp * 64];
                    const unsigned long long* wq = wr0 + kp * 8;
                    a0 = ffma2(hv, wq[0], a0); a1 = ffma2(hv, wq[1], a1);
                    a2 = ffma2(hv, wq[2], a2); a3 = ffma2(hv, wq[3], a3);
                    a4 = ffma2(hv, wq[4], a4); a5 = ffma2(hv, wq[5], a5);
                    a6 = ffma2(hv, wq[6], a6); a7 = ffma2(hv, wq[7], a7);
                }
                // x contribution for jown only
                const float*  xr = shx + (t & 1)*(BATCH*IN0) + b*IN0;
                const float4* wi = wi0 + kh * IN0;
                #pragma unroll
                for (int d = 0; d < IN0; ++d) {
                    float xv = xr[d]; float4 w = wi[d];
                    xi = fmaf(xv, w.x, xi); xf = fmaf(xv, w.y, xf);
                    xg = fmaf(xv, w.z, xg); xo = fmaf(xv, w.w, xo);
                }
                // publish 8 partial sums
                float* pp = part + tid * 8;
                float lo, hi;
                unpack2(a0, lo, hi); pp[0] = lo + hi;
                unpack2(a1, lo, hi); pp[1] = lo + hi;
                unpack2(a2, lo, hi); pp[2] = lo + hi;
                unpack2(a3, lo, hi); pp[3] = lo + hi;
                unpack2(a4, lo, hi); pp[4] = lo + hi;
                unpack2(a5, lo, hi); pp[5] = lo + hi;
                unpack2(a6, lo, hi); pp[6] = lo + hi;
                unpack2(a7, lo, hi); pp[7] = lo + hi;
            }
            // fused FC for h1[t-2] (needs sh_h1)
            if (t >= 2) {
                mbar_wait_parity(mb1, par);
                if (bid < BATCH) {
                    int jA = rt_, jB = rt_ + 128;
                    float vA = sh_h1f[(jA >> 1)*128 + bid*2 + (jA & 1)];
                    float vB = sh_h1f[(jB >> 1)*128 + bid*2 + (jB & 1)];
                    float p = fmaxf(vA, 0.f)*wfc0 + fmaxf(vB, 0.f)*wfc1;
                    p = warp_reduce(p);
                    if ((rt_ & 31) == 0) red4[rt_ >> 5] = p;
                }
            }
            asm volatile("bar.sync 1, 128;" ::: "memory");
            if (t < S_LEN) {
                const float* po = part + (tid ^ 64) * 8;
                const float* ps = part + tid * 8;
                float gi = ps[kh*4+0] + po[kh*4+0] + bG0 + xi;
                float gf = ps[kh*4+1] + po[kh*4+1] + bG1 + xf;
                float gg = ps[kh*4+2] + po[kh*4+2] + bG2 + xg;
                float go = ps[kh*4+3] + po[kh*4+3] + bG3 + xo;
                gi = sigmoidf_(gi); gf = sigmoidf_(gf);
                gg = tanh_acc(gg);  go = sigmoidf_(go);
                c = gf*c + gi*gg;
                float h = go * tanh_acc(c);
                g_h0buf[(t + 1) & 1][(bid*64 + b)*2 + kh] = h;
            }
            if (t >= 2 && bid < BATCH && rt_ == 0)
                out[(t - 2)*BATCH + bid] = red4[0]+red4[1]+red4[2]+red4[3] + bfc0;
        } else {
            // ================= layer1 (k-half) ==============================
            if (t >= 1) {
                unsigned long long a0=0,a1=0,a2=0,a3=0,a4=0,a5=0,a6=0,a7=0;
                mbar_wait_parity(mb0, par);
                {
                    const unsigned long long* hp = sh_h0u + (size_t)kpb * 64 + b;
                    #pragma unroll 8
                    for (int kp = 0; kp < KPH; ++kp) {
                        unsigned long long hv = hp[kp * 64];
                        const unsigned long long* wq = wri1 + kp * 8;
                        a0 = ffma2(hv, wq[0], a0); a1 = ffma2(hv, wq[1], a1);
                        a2 = ffma2(hv, wq[2], a2); a3 = ffma2(hv, wq[3], a3);
                        a4 = ffma2(hv, wq[4], a4); a5 = ffma2(hv, wq[5], a5);
                        a6 = ffma2(hv, wq[6], a6); a7 = ffma2(hv, wq[7], a7);
                    }
                }
                mbar_wait_parity(mb1, par);
                {
                    const unsigned long long* hp = sh_h1u + (size_t)kpb * 64 + b;
                    #pragma unroll 8
                    for (int kp = 0; kp < KPH; ++kp) {
                        unsigned long long hv = hp[kp * 64];
                        const unsigned long long* wq = wrh1 + kp * 8;
                        a0 = ffma2(hv, wq[0], a0); a1 = ffma2(hv, wq[1], a1);
                        a2 = ffma2(hv, wq[2], a2); a3 = ffma2(hv, wq[3], a3);
                        a4 = ffma2(hv, wq[4], a4); a5 = ffma2(hv, wq[5], a5);
                        a6 = ffma2(hv, wq[6], a6); a7 = ffma2(hv, wq[7], a7);
                    }
                }
                float* pp = part + tid * 8;
                float lo, hi;
                unpack2(a0, lo, hi); pp[0] = lo + hi;
                unpack2(a1, lo, hi); pp[1] = lo + hi;
                unpack2(a2, lo, hi); pp[2] = lo + hi;
                unpack2(a3, lo, hi); pp[3] = lo + hi;
                unpack2(a4, lo, hi); pp[4] = lo + hi;
                unpack2(a5, lo, hi); pp[5] = lo + hi;
                unpack2(a6, lo, hi); pp[6] = lo + hi;
                unpack2(a7, lo, hi); pp[7] = lo + hi;
                asm volatile("bar.sync 2, 128;" ::: "memory");
                const float* po = part + (tid ^ 64) * 8;
                float gi = pp[kh*4+0] + po[kh*4+0] + bG0;
                float gf = pp[kh*4+1] + po[kh*4+1] + bG1;
                float gg = pp[kh*4+2] + po[kh*4+2] + bG2;
                float go = pp[kh*4+3] + po[kh*4+3] + bG3;
                gi = sigmoidf_(gi); gf = sigmoidf_(gf);
                gg = tanh_acc(gg);  go = sigmoidf_(go);
                c = gf*c + gi*gg;
                float h = go * tanh_acc(c);
                g_h1buf[(t + 1) & 1][(bid*64 + b)*2 + kh] = h;
            }
        }

        // ---- global step barrier ------------------------------------------
        __syncthreads();                       // all stores issued CTA-wide
        if (tid == 0) red_rel_add(&g_bar);
        if (t + 1 < S_LEN) {                   // stage x[t+1] during wait
            const float* xs = x + (size_t)(t + 1)*BATCH*IN0;
            float* xd = shx + ((t + 1) & 1)*(BATCH*IN0);
            for (int idx = tid; idx < BATCH*IN0; idx += NT) xd[idx] = xs[idx];
        }
        if (tid == 0) {
            unsigned target = (unsigned)NB * (unsigned)(t + 1);
            unsigned v = ld_acq(&g_bar);
            int spins = 0;
            while (v < target) {
                if (++spins > 4) __nanosleep(32);
                v = ld_acq(&g_bar);
            }
        }
        __syncthreads();
    }

    // ---- final FC row: h1[4095] in g_h1buf[1] ------------------------------
    if (role == 0 && bid < BATCH) {
        int jA = rt_, jB = rt_ + 128;
        float vA = __ldcg(&g_h1buf[1][(jA >> 1)*128 + bid*2 + (jA & 1)]);
        float vB = __ldcg(&g_h1buf[1][(jB >> 1)*128 + bid*2 + (jB & 1)]);
        float p = fmaxf(vA, 0.f)*wfc0 + fmaxf(vB, 0.f)*wfc1;
        p = warp_reduce(p);
        if ((rt_ & 31) == 0) red4[rt_ >> 5] = p;
        asm volatile("bar.sync 1, 128;" ::: "memory");
        if (rt_ == 0)
            out[(S_LEN - 1)*BATCH + bid] = red4[0]+red4[1]+red4[2]+red4[3] + bfc0;
    }
}

// ---------------------------------------------------------------------------
// Init: reset barrier counter; transpose h0 into pair-interleaved buffers.
// g_h0buf[0] = initial h0 (read at t=0); g_h1buf[1] = initial h1 (read t=1).
// ---------------------------------------------------------------------------
extern "C" __global__ void lstm_init(const float* __restrict__ h0)
{
    int i = blockIdx.x * blockDim.x + threadIdx.x;
    if (i == 0) g_bar = 0u;
    for (int idx = i; idx < 2 * HID * BATCH; idx += gridDim.x * blockDim.x) {
        int l = idx >> 14;
        int r = idx & 16383;
        int k = r >> 6;
        int b = r & 63;
        float v = h0[(l*BATCH + b)*HID + k];
        int di = ((k >> 1)*64 + b)*2 + (k & 1);
        if (l == 0) g_h0buf[0][di] = v;
        else        g_h1buf[1][di] = v;
    }
}

// ---------------------------------------------------------------------------
extern "C" void kernel_launch(void* const* d_in, const int* in_sizes, int n_in,
                              void* d_out, int out_size)
{
    const float* x    = (const float*)d_in[0];
    const float* h0   = (const float*)d_in[1];
    const float* c0   = (const float*)d_in[2];
    const float* Wih0 = (const float*)d_in[3];
    const float* Whh0 = (const float*)d_in[4];
    const float* bih0 = (const float*)d_in[5];
    const float* bhh0 = (const float*)d_in[6];
    const float* Wih1 = (const float*)d_in[7];
    const float* Whh1 = (const float*)d_in[8];
    const float* bih1 = (const float*)d_in[9];
    const float* bhh1 = (const float*)d_in[10];
    const float* Wfc  = (const float*)d_in[11];
    const float* bfc  = (const float*)d_in[12];
    float* out = (float*)d_out;

    cudaFuncSetAttribute(lstm_fused, cudaFuncAttributeMaxDynamicSharedMemorySize, SMEM_TOTAL);

    lstm_init<<<64, 256>>>(h0);
    lstm_fused<<<NB, NT, SMEM_TOTAL>>>(x, c0, Wih0, Whh0, bih0, bhh0,
                                       Wih1, Whh1, bih1, bhh1, Wfc, bfc, out);
}

// round 4
// speedup vs baseline: 2.4702x; 1.0163x over previous
#include <cuda_runtime.h>
#include <cstdint>

// ---------------------------------------------------------------------------
// Fused 2-layer LSTM, S=4096, B=64, I=14, H=256, O=1 (gate order i,f,g,o)
//
// Batch elements are independent -> partition batch into 8 groups of 8.
// Each group = 16 CTAs holding ONE full weight replica in smem (192KB/CTA).
// CTA (gid, ci) owns hidden j-slice [ci*16, ci*16+16) of BOTH layers for its
// group's 8 batch elements. Per step each CTA exchanges only its group's h
// (16KB load / 1KB store) through L2, and groups sync with a private
// 16-arrival release/acquire barrier -> groups are fully decoupled.
//
// Pipeline per iteration t: layer0 computes h0[t], layer1 computes h1[t-1],
// FC emits out[t-2]. Thread = (kq, jl, b): kq0 = layer0 k-half + Wih1 gemm,
// kq1 = layer0 k-half + Whh1 gemm (192 k-pairs each, balanced). Partials
// combined via a float4 smem exchange; kq0 finalizes activations and c.
// ---------------------------------------------------------------------------

#define S_LEN  4096
#define BATCH  64
#define IN0    14
#define HID    256
#define NB     128
#define NT     256
#define NGRP   8
#define GCTAS  16
#define JL     16        // j per CTA
#define BG     8         // batch per group
#define HBUF   (HID*BG)  // 2048 floats = 8KB per layer per group

// ---- global scratch --------------------------------------------------------
__device__ float    g_h0x[NGRP][2][HBUF];   // [(kp*8+b)*2 + (k&1)]
__device__ float    g_h1x[NGRP][2][HBUF];
__device__ unsigned g_barG[NGRP * 32];      // 128B stride per group

// ---- packed fp32x2 helpers -------------------------------------------------
__device__ __forceinline__ unsigned long long pack2(float x, float y) {
    unsigned long long r;
    asm("mov.b64 %0, {%1,%2};" : "=l"(r) : "f"(x), "f"(y));
    return r;
}
__device__ __forceinline__ void unpack2(unsigned long long v, float& x, float& y) {
    asm("mov.b64 {%0,%1}, %2;" : "=f"(x), "=f"(y) : "l"(v));
}
__device__ __forceinline__ unsigned long long ffma2(unsigned long long a,
                                                    unsigned long long b,
                                                    unsigned long long c) {
    unsigned long long d;
    asm("fma.rn.f32x2 %0, %1, %2, %3;" : "=l"(d) : "l"(a), "l"(b), "l"(c));
    return d;
}
__device__ __forceinline__ float sum2(unsigned long long v) {
    float lo, hi; unpack2(v, lo, hi); return lo + hi;
}

// ---- activations -----------------------------------------------------------
__device__ __forceinline__ float sigmoidf_(float v) {
    return 1.0f / (1.0f + __expf(-v));
}
__device__ __forceinline__ float tanh_acc(float v) {
    float a = fabsf(v);
    float e = __expf(-2.0f * a);
    float r = __fdividef(1.0f - e, 1.0f + e);
    return v < 0.0f ? -r : r;
}

// ---- sync primitives -------------------------------------------------------
__device__ __forceinline__ void red_rel_add(unsigned* p) {
    asm volatile("red.release.gpu.global.add.u32 [%0], %1;" :: "l"(p), "r"(1u) : "memory");
}
__device__ __forceinline__ unsigned ld_acq(const unsigned* p) {
    unsigned v;
    asm volatile("ld.acquire.gpu.global.u32 %0, [%1];" : "=r"(v) : "l"(p) : "memory");
    return v;
}
__device__ __forceinline__ void cp16(uint32_t dst, const void* src) {
    asm volatile("cp.async.cg.shared.global [%0], [%1], 16;" :: "r"(dst), "l"(src));
}
__device__ __forceinline__ void mbar_init(uint32_t a, uint32_t cnt) {
    asm volatile("mbarrier.init.shared.b64 [%0], %1;" :: "r"(a), "r"(cnt) : "memory");
}
__device__ __forceinline__ void cp_arrive_noinc(uint32_t a) {
    asm volatile("cp.async.mbarrier.arrive.noinc.shared.b64 [%0];" :: "r"(a) : "memory");
}
__device__ __forceinline__ void mbar_wait_parity(uint32_t addr, uint32_t parity) {
    asm volatile(
        "{\n\t.reg .pred P;\n"
        "MW_%=:\n\t"
        "mbarrier.try_wait.parity.shared::cta.b64 P, [%0], %1;\n\t"
        "@!P bra MW_%=;\n\t}"
        :: "r"(addr), "r"(parity) : "memory");
}
__device__ __forceinline__ float warp_reduce(float p) {
    #pragma unroll
    for (int o = 16; o > 0; o >>= 1) p += __shfl_xor_sync(0xffffffffu, p, o);
    return p;
}

// ---- smem layout (bytes) ---------------------------------------------------
// weights stored as ull[(kp*16 + jl)*4 + gate]
#define SH_W0    0         // 65536  Whh0 slice  (kp 0..127)
#define SH_WI1   65536     // 65536  Wih1 slice
#define SH_WH1   131072    // 65536  Whh1 slice
#define SH_WI0   196608    // 3584   float4 wi0[16][14]
#define SH_H0    200192    // 8192   ull[kp128][b8]
#define SH_H1    208384    // 8192
#define SH_PL0   216576    // 2048   float4[128] (kq1 layer0 partials)
#define SH_PL1   218624    // 2048   float4[128] (kq1 layer1 partials)
#define SH_X     220672    // 896    float[2][8*14]
#define SH_RED   221568    // 32
#define SH_MBAR  221600    // 16
#define SMEM_TOTAL 221632

extern "C" __global__ void __launch_bounds__(NT, 1)
lstm_fused(const float* __restrict__ x,   const float* __restrict__ c0,
           const float* __restrict__ Wih0, const float* __restrict__ Whh0,
           const float* __restrict__ bih0, const float* __restrict__ bhh0,
           const float* __restrict__ Wih1, const float* __restrict__ Whh1,
           const float* __restrict__ bih1, const float* __restrict__ bhh1,
           const float* __restrict__ Wfc,  const float* __restrict__ bfc,
           float* __restrict__ out)
{
    extern __shared__ char smem[];
    unsigned long long* w0u  = (unsigned long long*)(smem + SH_W0);
    unsigned long long* wi1u = (unsigned long long*)(smem + SH_WI1);
    unsigned long long* wh1u = (unsigned long long*)(smem + SH_WH1);
    float4*             wi0  = (float4*)(smem + SH_WI0);
    unsigned long long* sh_h0u = (unsigned long long*)(smem + SH_H0);
    unsigned long long* sh_h1u = (unsigned long long*)(smem + SH_H1);
    float*              sh_h1f = (float*)(smem + SH_H1);
    float4*             pl0  = (float4*)(smem + SH_PL0);
    float4*             pl1  = (float4*)(smem + SH_PL1);
    float*              shx  = (float*)(smem + SH_X);
    float*              red4 = (float*)(smem + SH_RED);

    const uint32_t smem_h0 = (uint32_t)__cvta_generic_to_shared(smem + SH_H0);
    const uint32_t smem_h1 = (uint32_t)__cvta_generic_to_shared(smem + SH_H1);
    const uint32_t mb0     = (uint32_t)__cvta_generic_to_shared(smem + SH_MBAR);
    const uint32_t mb1     = mb0 + 8;

    const int tid = threadIdx.x;
    const int bid = blockIdx.x;
    const int gid = bid >> 4;           // group 0..7
    const int ci  = bid & 15;           // cta-in-group
    const int kq  = tid >> 7;           // k-half role
    const int f   = tid & 127;
    const int jl  = f >> 3;             // 0..15
    const int b   = f & 7;              // batch-local 0..7
    const int jglob = ci * JL + jl;
    const int bglob = gid * BG + b;

    if (tid == 0) { mbar_init(mb0, NT); mbar_init(mb1, NT); }

    // ---- preload weight slices (coalesced over k) --------------------------
    for (int e = tid; e < 128 * 16 * 4; e += NT) {
        int kp = e & 127;
        int r  = e >> 7;                // 0..63
        int wjl = r >> 2, gsel = r & 3;
        int row = (gsel * HID + ci * JL + wjl) * HID + 2 * kp;
        int slot = (kp * 16 + wjl) * 4 + gsel;
        w0u [slot] = pack2(Whh0[row], Whh0[row + 1]);
        wi1u[slot] = pack2(Wih1[row], Wih1[row + 1]);
        wh1u[slot] = pack2(Whh1[row], Whh1[row + 1]);
    }
    for (int e = tid; e < JL * IN0; e += NT) {
        int wjl = e / IN0, d = e % IN0;
        int jg = ci * JL + wjl;
        wi0[wjl * IN0 + d] = make_float4(
            Wih0[(0*HID + jg)*IN0 + d], Wih0[(1*HID + jg)*IN0 + d],
            Wih0[(2*HID + jg)*IN0 + d], Wih0[(3*HID + jg)*IN0 + d]);
    }

    // ---- per-thread state (kq0 finalizes) ----------------------------------
    float b00, b01, b02, b03, b10, b11, b12, b13, cL0, cL1;
    b00 = bih0[0*HID+jglob] + bhh0[0*HID+jglob];
    b01 = bih0[1*HID+jglob] + bhh0[1*HID+jglob];
    b02 = bih0[2*HID+jglob] + bhh0[2*HID+jglob];
    b03 = bih0[3*HID+jglob] + bhh0[3*HID+jglob];
    b10 = bih1[0*HID+jglob] + bhh1[0*HID+jglob];
    b11 = bih1[1*HID+jglob] + bhh1[1*HID+jglob];
    b12 = bih1[2*HID+jglob] + bhh1[2*HID+jglob];
    b13 = bih1[3*HID+jglob] + bhh1[3*HID+jglob];
    cL0 = c0[bglob*HID + jglob];
    cL1 = c0[(BATCH + bglob)*HID + jglob];
    const float wfcA = Wfc[f];
    const float wfcB = Wfc[f + 128];
    const float bfc0 = bfc[0];

    // stage x[0] for this group's batch slice
    for (int e = tid; e < BG*IN0; e += NT)
        shx[e] = x[(size_t)gid*BG*IN0 + e];
    __syncthreads();

    unsigned* bar = &g_barG[gid * 32];

    for (int t = 0; t <= S_LEN; ++t) {
        const uint32_t par = (uint32_t)(t & 1);

        // ---- issue cp.async loads (h0 -> mb0, h1 -> mb1) -------------------
        {
            const float4* s0 = (const float4*)g_h0x[gid][par];
            const float4* s1 = (const float4*)g_h1x[gid][par];
            cp16(smem_h0 + tid*16,          s0 + tid);
            cp16(smem_h0 + (tid+256)*16,    s0 + tid + 256);
            cp_arrive_noinc(mb0);
            cp16(smem_h1 + tid*16,          s1 + tid);
            cp16(smem_h1 + (tid+256)*16,    s1 + tid + 256);
            cp_arrive_noinc(mb1);
        }

        mbar_wait_parity(mb0, par);

        unsigned long long a0=0,a1=0,a2=0,a3=0;   // layer0 partial (this k-half)
        unsigned long long e0=0,e1=0,e2=0,e3=0;   // layer1 partial (this matrix)
        float xg0=0.f, xg1=0.f, xg2=0.f, xg3=0.f;

        if (kq == 0) {
            if (t < S_LEN) {
                const unsigned long long* hp = sh_h0u + b;
                const unsigned long long* wq = w0u + jl*4;
                #pragma unroll 8
                for (int kp = 0; kp < 64; ++kp) {
                    unsigned long long hv = hp[kp*8];
                    const unsigned long long* w = wq + kp*64;
                    ulonglong2 wA = *(const ulonglong2*)(w);
                    ulonglong2 wB = *(const ulonglong2*)(w + 2);
                    a0 = ffma2(hv, wA.x, a0); a1 = ffma2(hv, wA.y, a1);
                    a2 = ffma2(hv, wB.x, a2); a3 = ffma2(hv, wB.y, a3);
                }
                // x contribution
                const float*  xr = shx + (t & 1)*(BG*IN0) + b*IN0;
                const float4* wi = wi0 + jl*IN0;
                #pragma unroll
                for (int d = 0; d < IN0; ++d) {
                    float xv = xr[d]; float4 w = wi[d];
                    xg0 = fmaf(xv, w.x, xg0); xg1 = fmaf(xv, w.y, xg1);
                    xg2 = fmaf(xv, w.z, xg2); xg3 = fmaf(xv, w.w, xg3);
                }
            }
            if (t >= 1) {              // layer1 input gemm: Wih1 x h0[t-1]
                const unsigned long long* hp = sh_h0u + b;
                const unsigned long long* wq = wi1u + jl*4;
                #pragma unroll 8
                for (int kp = 0; kp < 128; ++kp) {
                    unsigned long long hv = hp[kp*8];
                    const unsigned long long* w = wq + kp*64;
                    ulonglong2 wA = *(const ulonglong2*)(w);
                    ulonglong2 wB = *(const ulonglong2*)(w + 2);
                    e0 = ffma2(hv, wA.x, e0); e1 = ffma2(hv, wA.y, e1);
                    e2 = ffma2(hv, wB.x, e2); e3 = ffma2(hv, wB.y, e3);
                }
            }
        } else {
            if (t < S_LEN) {           // layer0 upper k-half
                const unsigned long long* hp = sh_h0u + 64*8 + b;
                const unsigned long long* wq = w0u + 64*64 + jl*4;
                #pragma unroll 8
                for (int kp = 0; kp < 64; ++kp) {
                    unsigned long long hv = hp[kp*8];
                    const unsigned long long* w = wq + kp*64;
                    ulonglong2 wA = *(const ulonglong2*)(w);
                    ulonglong2 wB = *(const ulonglong2*)(w + 2);
                    a0 = ffma2(hv, wA.x, a0); a1 = ffma2(hv, wA.y, a1);
                    a2 = ffma2(hv, wB.x, a2); a3 = ffma2(hv, wB.y, a3);
                }
            }
            mbar_wait_parity(mb1, par);
            if (t >= 1) {              // layer1 recurrent gemm: Whh1 x h1[t-2]
                const unsigned long long* hp = sh_h1u + b;
                const unsigned long long* wq = wh1u + jl*4;
                #pragma unroll 8
                for (int kp = 0; kp < 128; ++kp) {
                    unsigned long long hv = hp[kp*8];
                    const unsigned long long* w = wq + kp*64;
                    ulonglong2 wA = *(const ulonglong2*)(w);
                    ulonglong2 wB = *(const ulonglong2*)(w + 2);
                    e0 = ffma2(hv, wA.x, e0); e1 = ffma2(hv, wA.y, e1);
                    e2 = ffma2(hv, wB.x, e2); e3 = ffma2(hv, wB.y, e3);
                }
            }
            pl0[f] = make_float4(sum2(a0), sum2(a1), sum2(a2), sum2(a3));
            pl1[f] = make_float4(sum2(e0), sum2(e1), sum2(e2), sum2(e3));
        }
        __syncthreads();

        if (kq == 0) {
            float4 p0 = pl0[f];
            float4 p1 = pl1[f];
            if (t < S_LEN) {           // finalize layer0 -> h0[t]
                float gi = sum2(a0) + p0.x + b00 + xg0;
                float gf = sum2(a1) + p0.y + b01 + xg1;
                float gg = sum2(a2) + p0.z + b02 + xg2;
                float go = sum2(a3) + p0.w + b03 + xg3;
                gi = sigmoidf_(gi); gf = sigmoidf_(gf);
                gg = tanh_acc(gg);  go = sigmoidf_(go);
                cL0 = gf*cL0 + gi*gg;
                float h = go * tanh_acc(cL0);
                g_h0x[gid][(t+1)&1][((ci*8 + (jl>>1))*8 + b)*2 + (jl&1)] = h;
            }
            if (t >= 1) {              // finalize layer1 -> h1[t-1]
                float gi = sum2(e0) + p1.x + b10;
                float gf = sum2(e1) + p1.y + b11;
                float gg = sum2(e2) + p1.z + b12;
                float go = sum2(e3) + p1.w + b13;
                gi = sigmoidf_(gi); gf = sigmoidf_(gf);
                gg = tanh_acc(gg);  go = sigmoidf_(go);
                cL1 = gf*cL1 + gi*gg;
                float h = go * tanh_acc(cL1);
                g_h1x[gid][(t+1)&1][((ci*8 + (jl>>1))*8 + b)*2 + (jl&1)] = h;
            }
        } else if (t >= 2 && ci < BG) {
            // ---- FC for out[t-2][gid*8+ci] from sh_h1 (= h1[t-2]) ----------
            int j1 = f, j2 = f + 128;
            float vA = sh_h1f[(j1>>1)*16 + ci*2 + (j1&1)];
            float vB = sh_h1f[(j2>>1)*16 + ci*2 + (j2&1)];
            float p = fmaxf(vA, 0.f)*wfcA + fmaxf(vB, 0.f)*wfcB;
            p = warp_reduce(p);
            if ((f & 31) == 0) red4[f >> 5] = p;
            asm volatile("bar.sync 3, 128;" ::: "memory");
            if (f == 0)
                out[(size_t)(t-2)*BATCH + gid*BG + ci] =
                    red4[0]+red4[1]+red4[2]+red4[3] + bfc0;
        }

        // ---- group barrier -------------------------------------------------
        __syncthreads();
        if (tid == 0) red_rel_add(bar);
        if (t + 1 < S_LEN) {           // stage x[t+1] during wait
            const float* xs = x + ((size_t)(t+1)*BATCH + gid*BG)*IN0;
            float* xd = shx + ((t+1)&1)*(BG*IN0);
            for (int e = tid; e < BG*IN0; e += NT) xd[e] = xs[e];
        }
        if (tid == 0) {
            unsigned target = (unsigned)GCTAS * (unsigned)(t + 1);
            unsigned v = ld_acq(bar);
            int spins = 0;
            while (v < target) {
                if (++spins > 4) __nanosleep(32);
                v = ld_acq(bar);
            }
        }
        __syncthreads();
    }

    // ---- final FC row 4095: h1[4095] in g_h1x[gid][1] ----------------------
    if (kq == 1 && ci < BG) {
        int j1 = f, j2 = f + 128;
        float vA = __ldcg(&g_h1x[gid][1][(j1>>1)*16 + ci*2 + (j1&1)]);
        float vB = __ldcg(&g_h1x[gid][1][(j2>>1)*16 + ci*2 + (j2&1)]);
        float p = fmaxf(vA, 0.f)*wfcA + fmaxf(vB, 0.f)*wfcB;
        p = warp_reduce(p);
        if ((f & 31) == 0) red4[f >> 5] = p;
        asm volatile("bar.sync 3, 128;" ::: "memory");
        if (f == 0)
            out[(size_t)(S_LEN-1)*BATCH + gid*BG + ci] =
                red4[0]+red4[1]+red4[2]+red4[3] + bfc0;
    }
}

// ---------------------------------------------------------------------------
// Init: reset group barriers; scatter h0 init into exchange buffers.
// g_h0x[g][0] = h0 layer0 (read at t=0); g_h1x[g][1] = h0 layer1 (read t=1).
// ---------------------------------------------------------------------------
extern "C" __global__ void lstm_init(const float* __restrict__ h0)
{
    int i = blockIdx.x * blockDim.x + threadIdx.x;
    if (i < NGRP * 32) g_barG[i] = 0u;
    for (int idx = i; idx < 2 * NGRP * HBUF; idx += gridDim.x * blockDim.x) {
        int l = idx >> 14;              // layer
        int rest = idx & 16383;
        int g = rest >> 11;
        int q = rest & 2047;            // = (kp*8+b)*2+par
        int kp = q >> 4;
        int b  = (q >> 1) & 7;
        int par = q & 1;
        int k = kp*2 + par;
        float v = h0[(l*BATCH + g*BG + b)*HID + k];
        if (l == 0) g_h0x[g][0][q] = v;
        else        g_h1x[g][1][q] = v;
    }
}

// ---------------------------------------------------------------------------
extern "C" void kernel_launch(void* const* d_in, const int* in_sizes, int n_in,
                              void* d_out, int out_size)
{
    const float* x    = (const float*)d_in[0];
    const float* h0   = (const float*)d_in[1];
    const float* c0   = (const float*)d_in[2];
    const float* Wih0 = (const float*)d_in[3];
    const float* Whh0 = (const float*)d_in[4];
    const float* bih0 = (const float*)d_in[5];
    const float* bhh0 = (const float*)d_in[6];
    const float* Wih1 = (const float*)d_in[7];
    const float* Whh1 = (const float*)d_in[8];
    const float* bih1 = (const float*)d_in[9];
    const float* bhh1 = (const float*)d_in[10];
    const float* Wfc  = (const float*)d_in[11];
    const float* bfc  = (const float*)d_in[12];
    float* out = (float*)d_out;

    cudaFuncSetAttribute(lstm_fused, cudaFuncAttributeMaxDynamicSharedMemorySize, SMEM_TOTAL);

    lstm_init<<<64, 256>>>(h0);
    lstm_fused<<<NB, NT, SMEM_TOTAL>>>(x, c0, Wih0, Whh0, bih0, bhh0,
                                       Wih1, Whh1, bih1, bhh1, Wfc, bfc, out);
}

// round 5
// speedup vs baseline: 2.4755x; 1.0022x over previous
#include <cuda_runtime.h>
#include <cstdint>

// ---------------------------------------------------------------------------
// Fused 2-layer LSTM, S=4096, B=64, I=14, H=256, O=1 (gate order i,f,g,o)
//
// 8 batch groups x 16 CTAs; each CTA: full weight replica slice in smem,
// j-slice of 16 hidden units for 8 batch elems, BOTH layers.
// NT=512 (16 warps -> 4/SMSP) for latency hiding. Thread = (kq, jl, b):
//   all kq: layer0 k-quarter (32 kp)
//   kq0/kq1: layer1 Wih1 k-half (64 kp);  kq2/kq3: layer1 Whh1 k-half
//   kq3 folds the x[t] (I=14) contribution into its layer0 partial
//   kq0 finalizes layer0 -> h0[t];  kq1 finalizes layer1 -> h1[t-1] (+FC)
// Partials combined via smem float4 exchange + one __syncthreads.
// h exchanged through L2 (cp.async + 2 mbarriers), group-private
// 16-arrival release/acquire barrier per step.
// ---------------------------------------------------------------------------

#define S_LEN  4096
#define BATCH  64
#define IN0    14
#define HID    256
#define NB     128
#define NT     512
#define NGRP   8
#define GCTAS  16
#define JL     16
#define BG     8
#define HBUF   (HID*BG)

// ---- global scratch --------------------------------------------------------
__device__ float    g_h0x[NGRP][2][HBUF];   // [(kp*8+b)*2 + (k&1)]
__device__ float    g_h1x[NGRP][2][HBUF];
__device__ unsigned g_barG[NGRP * 32];

// ---- packed fp32x2 helpers -------------------------------------------------
__device__ __forceinline__ unsigned long long pack2(float x, float y) {
    unsigned long long r;
    asm("mov.b64 %0, {%1,%2};" : "=l"(r) : "f"(x), "f"(y));
    return r;
}
__device__ __forceinline__ void unpack2(unsigned long long v, float& x, float& y) {
    asm("mov.b64 {%0,%1}, %2;" : "=f"(x), "=f"(y) : "l"(v));
}
__device__ __forceinline__ unsigned long long ffma2(unsigned long long a,
                                                    unsigned long long b,
                                                    unsigned long long c) {
    unsigned long long d;
    asm("fma.rn.f32x2 %0, %1, %2, %3;" : "=l"(d) : "l"(a), "l"(b), "l"(c));
    return d;
}
__device__ __forceinline__ float sum2(unsigned long long v) {
    float lo, hi; unpack2(v, lo, hi); return lo + hi;
}

// ---- activations -----------------------------------------------------------
__device__ __forceinline__ float sigmoidf_(float v) {
    return 1.0f / (1.0f + __expf(-v));
}
__device__ __forceinline__ float tanh_acc(float v) {
    float a = fabsf(v);
    float e = __expf(-2.0f * a);
    float r = __fdividef(1.0f - e, 1.0f + e);
    return v < 0.0f ? -r : r;
}

// ---- sync primitives -------------------------------------------------------
__device__ __forceinline__ void red_rel_add(unsigned* p) {
    asm volatile("red.release.gpu.global.add.u32 [%0], %1;" :: "l"(p), "r"(1u) : "memory");
}
__device__ __forceinline__ unsigned ld_acq(const unsigned* p) {
    unsigned v;
    asm volatile("ld.acquire.gpu.global.u32 %0, [%1];" : "=r"(v) : "l"(p) : "memory");
    return v;
}
__device__ __forceinline__ void cp16(uint32_t dst, const void* src) {
    asm volatile("cp.async.cg.shared.global [%0], [%1], 16;" :: "r"(dst), "l"(src));
}
__device__ __forceinline__ void mbar_init(uint32_t a, uint32_t cnt) {
    asm volatile("mbarrier.init.shared.b64 [%0], %1;" :: "r"(a), "r"(cnt) : "memory");
}
__device__ __forceinline__ void cp_arrive_noinc(uint32_t a) {
    asm volatile("cp.async.mbarrier.arrive.noinc.shared.b64 [%0];" :: "r"(a) : "memory");
}
__device__ __forceinline__ void mbar_wait_parity(uint32_t addr, uint32_t parity) {
    asm volatile(
        "{\n\t.reg .pred P;\n"
        "MW_%=:\n\t"
        "mbarrier.try_wait.parity.shared::cta.b64 P, [%0], %1;\n\t"
        "@!P bra MW_%=;\n\t}"
        :: "r"(addr), "r"(parity) : "memory");
}
__device__ __forceinline__ float warp_reduce(float p) {
    #pragma unroll
    for (int o = 16; o > 0; o >>= 1) p += __shfl_xor_sync(0xffffffffu, p, o);
    return p;
}

// ---- smem layout (bytes) ---------------------------------------------------
// weights: ull slot (kp*16 + jl)*4 + gate
#define SH_W0    0          // 65536  Whh0
#define SH_WI1   65536      // 65536  Wih1
#define SH_WH1   131072     // 65536  Whh1
#define SH_WI0   196608     // 3584   float4 wi0[16][14]
#define SH_H0    200192     // 8192   ull[kp128][b8]
#define SH_H1    208384     // 8192
#define SH_PL0   216576     // 6144   float4[3][128]  L0 partials (kq1,2,3)
#define SH_PL1   222720     // 6144   float4[3][128]  L1 partials (kq0-ih, kq2, kq3)
#define SH_X     228864     // 896    float[2][112]
#define SH_RED   229760     // 32
#define SH_MBAR  229792     // 16
#define SMEM_TOTAL 229808

extern "C" __global__ void __launch_bounds__(NT, 1)
lstm_fused(const float* __restrict__ x,   const float* __restrict__ c0,
           const float* __restrict__ Wih0, const float* __restrict__ Whh0,
           const float* __restrict__ bih0, const float* __restrict__ bhh0,
           const float* __restrict__ Wih1, const float* __restrict__ Whh1,
           const float* __restrict__ bih1, const float* __restrict__ bhh1,
           const float* __restrict__ Wfc,  const float* __restrict__ bfc,
           float* __restrict__ out)
{
    extern __shared__ char smem[];
    unsigned long long* w0u    = (unsigned long long*)(smem + SH_W0);
    unsigned long long* wi1u   = (unsigned long long*)(smem + SH_WI1);
    unsigned long long* wh1u   = (unsigned long long*)(smem + SH_WH1);
    float4*             wi0    = (float4*)(smem + SH_WI0);
    unsigned long long* sh_h0u = (unsigned long long*)(smem + SH_H0);
    unsigned long long* sh_h1u = (unsigned long long*)(smem + SH_H1);
    float*              sh_h1f = (float*)(smem + SH_H1);
    float4*             pl0    = (float4*)(smem + SH_PL0);
    float4*             pl1    = (float4*)(smem + SH_PL1);
    float*              shx    = (float*)(smem + SH_X);
    float*              red4   = (float*)(smem + SH_RED);

    const uint32_t smem_h0 = (uint32_t)__cvta_generic_to_shared(smem + SH_H0);
    const uint32_t smem_h1 = (uint32_t)__cvta_generic_to_shared(smem + SH_H1);
    const uint32_t mb0     = (uint32_t)__cvta_generic_to_shared(smem + SH_MBAR);
    const uint32_t mb1     = mb0 + 8;

    const int tid = threadIdx.x;
    const int bid = blockIdx.x;
    const int gid = bid >> 4;
    const int ci  = bid & 15;
    const int kq  = tid >> 7;           // 0..3
    const int f   = tid & 127;
    const int jl  = f >> 3;
    const int b   = f & 7;
    const int jglob = ci * JL + jl;

    if (tid == 0) { mbar_init(mb0, NT); mbar_init(mb1, NT); }

    // ---- preload weight slices --------------------------------------------
    for (int e = tid; e < 128 * 16 * 4; e += NT) {
        int kp = e & 127;
        int r  = e >> 7;
        int wjl = r >> 2, gsel = r & 3;
        int row = (gsel * HID + ci * JL + wjl) * HID + 2 * kp;
        int slot = (kp * 16 + wjl) * 4 + gsel;
        w0u [slot] = pack2(Whh0[row], Whh0[row + 1]);
        wi1u[slot] = pack2(Wih1[row], Wih1[row + 1]);
        wh1u[slot] = pack2(Whh1[row], Whh1[row + 1]);
    }
    for (int e = tid; e < JL * IN0; e += NT) {
        int wjl = e / IN0, d = e % IN0;
        int jg = ci * JL + wjl;
        wi0[wjl * IN0 + d] = make_float4(
            Wih0[(0*HID + jg)*IN0 + d], Wih0[(1*HID + jg)*IN0 + d],
            Wih0[(2*HID + jg)*IN0 + d], Wih0[(3*HID + jg)*IN0 + d]);
    }

    // ---- per-role state ----------------------------------------------------
    const int bglob = gid * BG + b;
    float bs0 = 0.f, bs1 = 0.f, bs2 = 0.f, bs3 = 0.f, cst = 0.f;
    if (kq == 0) {            // layer0 finalizer
        bs0 = bih0[0*HID+jglob] + bhh0[0*HID+jglob];
        bs1 = bih0[1*HID+jglob] + bhh0[1*HID+jglob];
        bs2 = bih0[2*HID+jglob] + bhh0[2*HID+jglob];
        bs3 = bih0[3*HID+jglob] + bhh0[3*HID+jglob];
        cst = c0[bglob*HID + jglob];
    } else if (kq == 1) {     // layer1 finalizer
        bs0 = bih1[0*HID+jglob] + bhh1[0*HID+jglob];
        bs1 = bih1[1*HID+jglob] + bhh1[1*HID+jglob];
        bs2 = bih1[2*HID+jglob] + bhh1[2*HID+jglob];
        bs3 = bih1[3*HID+jglob] + bhh1[3*HID+jglob];
        cst = c0[(BATCH + bglob)*HID + jglob];
    }
    const float wfcA = Wfc[f];
    const float wfcB = Wfc[f + 128];
    const float bfc0 = bfc[0];

    for (int e = tid; e < BG*IN0; e += NT)
        shx[e] = x[(size_t)gid*BG*IN0 + e];
    __syncthreads();

    unsigned* bar = &g_barG[gid * 32];

    const int storeIdx = ((ci*8 + (jl>>1))*8 + b)*2 + (jl&1);

    for (int t = 0; t <= S_LEN; ++t) {
        const uint32_t par = (uint32_t)(t & 1);

        // ---- issue cp.async loads (h0 -> mb0, h1 -> mb1) -------------------
        {
            const float4* s0 = (const float4*)g_h0x[gid][par];
            const float4* s1 = (const float4*)g_h1x[gid][par];
            cp16(smem_h0 + tid*16, s0 + tid);
            cp_arrive_noinc(mb0);
            cp16(smem_h1 + tid*16, s1 + tid);
            cp_arrive_noinc(mb1);
        }

        mbar_wait_parity(mb0, par);

        // ---- layer0 k-quarter (all roles) ----------------------------------
        unsigned long long a0=0,a1=0,a2=0,a3=0;
        if (t < S_LEN) {
            const unsigned long long* hp = sh_h0u + kq*32*8 + b;
            const unsigned long long* wq = w0u + kq*32*64 + jl*4;
            #pragma unroll 8
            for (int kp = 0; kp < 32; ++kp) {
                unsigned long long hv = hp[kp*8];
                const unsigned long long* w = wq + kp*64;
                ulonglong2 wA = *(const ulonglong2*)(w);
                ulonglong2 wB = *(const ulonglong2*)(w + 2);
                a0 = ffma2(hv, wA.x, a0); a1 = ffma2(hv, wA.y, a1);
                a2 = ffma2(hv, wB.x, a2); a3 = ffma2(hv, wB.y, a3);
            }
        }
        float l0x = sum2(a0), l0y = sum2(a1), l0z = sum2(a2), l0w = sum2(a3);

        // kq3: fold x[t] contribution into its layer0 partial
        if (kq == 3 && t < S_LEN) {
            const float*  xr = shx + (t & 1)*(BG*IN0) + b*IN0;
            const float4* wi = wi0 + jl*IN0;
            #pragma unroll
            for (int d = 0; d < IN0; ++d) {
                float xv = xr[d]; float4 w = wi[d];
                l0x = fmaf(xv, w.x, l0x); l0y = fmaf(xv, w.y, l0y);
                l0z = fmaf(xv, w.z, l0z); l0w = fmaf(xv, w.w, l0w);
            }
        }
        if (kq != 0) pl0[(kq-1)*128 + f] = make_float4(l0x, l0y, l0z, l0w);

        // ---- layer1 half-GEMMs ---------------------------------------------
        unsigned long long e0=0,e1=0,e2=0,e3=0;
        if (kq < 2) {
            if (t >= 1) {                       // Wih1 x h0[t-1], half kq
                const unsigned long long* hp = sh_h0u + kq*64*8 + b;
                const unsigned long long* wq = wi1u + kq*64*64 + jl*4;
                #pragma unroll 8
                for (int kp = 0; kp < 64; ++kp) {
                    unsigned long long hv = hp[kp*8];
                    const unsigned long long* w = wq + kp*64;
                    ulonglong2 wA = *(const ulonglong2*)(w);
                    ulonglong2 wB = *(const ulonglong2*)(w + 2);
                    e0 = ffma2(hv, wA.x, e0); e1 = ffma2(hv, wA.y, e1);
                    e2 = ffma2(hv, wB.x, e2); e3 = ffma2(hv, wB.y, e3);
                }
            }
            if (kq == 0)
                pl1[f] = make_float4(sum2(e0), sum2(e1), sum2(e2), sum2(e3));
        } else {
            mbar_wait_parity(mb1, par);
            if (t >= 1) {                       // Whh1 x h1[t-2], half kq-2
                const int kh = kq - 2;
                const unsigned long long* hp = sh_h1u + kh*64*8 + b;
                const unsigned long long* wq = wh1u + kh*64*64 + jl*4;
                #pragma unroll 8
                for (int kp = 0; kp < 64; ++kp) {
                    unsigned long long hv = hp[kp*8];
                    const unsigned long long* w = wq + kp*64;
                    ulonglong2 wA = *(const ulonglong2*)(w);
                    ulonglong2 wB = *(const ulonglong2*)(w + 2);
                    e0 = ffma2(hv, wA.x, e0); e1 = ffma2(hv, wA.y, e1);
                    e2 = ffma2(hv, wB.x, e2); e3 = ffma2(hv, wB.y, e3);
                }
            }
            pl1[(kq-1)*128 + f] = make_float4(sum2(e0), sum2(e1), sum2(e2), sum2(e3));
        }
        __syncthreads();

        if (kq == 0) {
            // ---- finalize layer0 -> h0[t] ----------------------------------
            if (t < S_LEN) {
                float4 p1 = pl0[f], p2 = pl0[128+f], p3 = pl0[256+f];
                float gi = l0x + p1.x + p2.x + p3.x + bs0;
                float gf = l0y + p1.y + p2.y + p3.y + bs1;
                float gg = l0z + p1.z + p2.z + p3.z + bs2;
                float go = l0w + p1.w + p2.w + p3.w + bs3;
                gi = sigmoidf_(gi); gf = sigmoidf_(gf);
                gg = tanh_acc(gg);  go = sigmoidf_(go);
                cst = gf*cst + gi*gg;
                float h = go * tanh_acc(cst);
                g_h0x[gid][(t+1)&1][storeIdx] = h;
            }
        } else if (kq == 1) {
            // ---- finalize layer1 -> h1[t-1] --------------------------------
            if (t >= 1) {
                float4 p1 = pl1[f], p2 = pl1[128+f], p3 = pl1[256+f];
                float gi = sum2(e0) + p1.x + p2.x + p3.x + bs0;
                float gf = sum2(e1) + p1.y + p2.y + p3.y + bs1;
                float gg = sum2(e2) + p1.z + p2.z + p3.z + bs2;
                float go = sum2(e3) + p1.w + p2.w + p3.w + bs3;
                gi = sigmoidf_(gi); gf = sigmoidf_(gf);
                gg = tanh_acc(gg);  go = sigmoidf_(go);
                cst = gf*cst + gi*gg;
                float h = go * tanh_acc(cst);
                g_h1x[gid][(t+1)&1][storeIdx] = h;
            }
            // ---- fused FC for out[t-2] from sh_h1 (= h1[t-2]) --------------
            if (t >= 2 && ci < BG) {
                int j1 = f, j2 = f + 128;
                float vA = sh_h1f[(j1>>1)*16 + ci*2 + (j1&1)];
                float vB = sh_h1f[(j2>>1)*16 + ci*2 + (j2&1)];
                float p = fmaxf(vA, 0.f)*wfcA + fmaxf(vB, 0.f)*wfcB;
                p = warp_reduce(p);
                if ((f & 31) == 0) red4[f >> 5] = p;
                asm volatile("bar.sync 2, 128;" ::: "memory");
                if (f == 0)
                    out[(size_t)(t-2)*BATCH + gid*BG + ci] =
                        red4[0]+red4[1]+red4[2]+red4[3] + bfc0;
            }
        }

        // ---- group barrier -------------------------------------------------
        __syncthreads();
        if (tid == 0) red_rel_add(bar);
        if (t + 1 < S_LEN) {                    // stage x[t+1] during wait
            const float* xs = x + ((size_t)(t+1)*BATCH + gid*BG)*IN0;
            float* xd = shx + ((t+1)&1)*(BG*IN0);
            if (tid < BG*IN0) xd[tid] = xs[tid];
        }
        if (tid == 0) {
            unsigned target = (unsigned)GCTAS * (unsigned)(t + 1);
            unsigned v = ld_acq(bar);
            int spins = 0;
            while (v < target) {
                if (++spins > 4) __nanosleep(20);
                v = ld_acq(bar);
            }
        }
        __syncthreads();
    }

    // ---- final FC row 4095: h1[4095] in g_h1x[gid][1] ----------------------
    if (kq == 1 && ci < BG) {
        int j1 = f, j2 = f + 128;
        float vA = __ldcg(&g_h1x[gid][1][(j1>>1)*16 + ci*2 + (j1&1)]);
        float vB = __ldcg(&g_h1x[gid][1][(j2>>1)*16 + ci*2 + (j2&1)]);
        float p = fmaxf(vA, 0.f)*wfcA + fmaxf(vB, 0.f)*wfcB;
        p = warp_reduce(p);
        if ((f & 31) == 0) red4[f >> 5] = p;
        asm volatile("bar.sync 2, 128;" ::: "memory");
        if (f == 0)
            out[(size_t)(S_LEN-1)*BATCH + gid*BG + ci] =
                red4[0]+red4[1]+red4[2]+red4[3] + bfc0;
    }
}

// ---------------------------------------------------------------------------
// Init: reset group barriers; scatter h0 init into exchange buffers.
// ---------------------------------------------------------------------------
extern "C" __global__ void lstm_init(const float* __restrict__ h0)
{
    int i = blockIdx.x * blockDim.x + threadIdx.x;
    if (i < NGRP * 32) g_barG[i] = 0u;
    for (int idx = i; idx < 2 * NGRP * HBUF; idx += gridDim.x * blockDim.x) {
        int l = idx >> 14;
        int rest = idx & 16383;
        int g = rest >> 11;
        int q = rest & 2047;
        int kp = q >> 4;
        int b  = (q >> 1) & 7;
        int par = q & 1;
        int k = kp*2 + par;
        float v = h0[(l*BATCH + g*BG + b)*HID + k];
        if (l == 0) g_h0x[g][0][q] = v;
        else        g_h1x[g][1][q] = v;
    }
}

// ---------------------------------------------------------------------------
extern "C" void kernel_launch(void* const* d_in, const int* in_sizes, int n_in,
                              void* d_out, int out_size)
{
    const float* x    = (const float*)d_in[0];
    const float* h0   = (const float*)d_in[1];
    const float* c0   = (const float*)d_in[2];
    const float* Wih0 = (const float*)d_in[3];
    const float* Whh0 = (const float*)d_in[4];
    const float* bih0 = (const float*)d_in[5];
    const float* bhh0 = (const float*)d_in[6];
    const float* Wih1 = (const float*)d_in[7];
    const float* Whh1 = (const float*)d_in[8];
    const float* bih1 = (const float*)d_in[9];
    const float* bhh1 = (const float*)d_in[10];
    const float* Wfc  = (const float*)d_in[11];
    const float* bfc  = (const float*)d_in[12];
    float* out = (float*)d_out;

    cudaFuncSetAttribute(lstm_fused, cudaFuncAttributeMaxDynamicSharedMemorySize, SMEM_TOTAL);

    lstm_init<<<64, 256>>>(h0);
    lstm_fused<<<NB, NT, SMEM_TOTAL>>>(x, c0, Wih0, Whh0, bih0, bhh0,
                                       Wih1, Whh1, bih1, bhh1, Wfc, bfc, out);
}